// round 7
// baseline (speedup 1.0000x reference)
#include <cuda_runtime.h>

// rate_loss: x (32,64,128,128) fp32 -> scalar f32
//
//  k_hist  : one pass; u = floor(5x)+32 in [0,64); per-thread u16-packed
//            counters (word = (u&31)*256+tid, conflict-free; inc = 1 or 1<<16
//            selected by sign(x)); 4-deep front-batched float4 loads;
//            cold outliers (|x|>=6.4; never for this data) -> global atomics
//  k_prep  : 1 block; vmin from lowest nonzero key; table
//            {g[i], c[i] = hist_add[i] + 1e-8 - left_i*g[i]}  (fp64 math)
//  k_loss  : one pass; nl = fma(x, g[i], c[i]); one log2 per 4-element product
//  k_final : out = -sum/n; then resets d_hist/d_sum for the next replay
//            (globals are zero-init at load, so run 1 is also correct)

#define NBINS_MAX 200
#define BPU_I     5
#define GLEN      195   // NBINS_MAX - BPU
#define HLEN      196   // NBINS_MAX - BPU + 1
#define KBINS     1024  // global absolute-key histogram, keys [-512,511]
#define KOFF      512
#define WBINS     64    // hot window, keys [-32,32)  (|x| < 6.4)
#define WOFF      32
#define NPAIR     32    // u32 words per thread (2 u16 bins each)

__device__ unsigned int d_hist[KBINS];   // zero-initialized at module load
__device__ double       d_sum;           // zero-initialized at module load
__device__ float2       d_gh[GLEN];      // {g[i], c[i]}
__device__ float        d_voff;          // -5*vmin_new

// ---------------------------------------------------------------- histogram
// word index = (u&31)*256 + tid -> bank = tid&31 : conflict-free always.
// low u16 = bins 0..31 (x<0), high u16 = bins 32..63 (x>=0).
__device__ __forceinline__ void bump(float xv, unsigned int u,
                                     unsigned int* __restrict__ hw) {
    unsigned int inc = (xv >= 0.0f) ? 65536u : 1u;
    hw[(u & 31u) * 256] += inc;              // LDS.32 + IADD + STS.32
}
__device__ __forceinline__ void bump_slow(unsigned int u) {
    int k = (int)u - WOFF;                   // raw key floor(5x)
    k = min(KOFF - 1, max(-KOFF, k));
    atomicAdd(&d_hist[k + KOFF], 1u);        // never taken for N(0,1) data
}
__device__ __forceinline__ unsigned int key_of(float v) {
    return (unsigned int)__float2int_rd(fmaf(v, 5.0f, 32.0f));
}
__device__ __forceinline__ void group4(float4 a, unsigned int* __restrict__ hw) {
    unsigned int u0 = key_of(a.x), u1 = key_of(a.y);
    unsigned int u2 = key_of(a.z), u3 = key_of(a.w);
    if ((u0 | u1 | u2 | u3) < WBINS) {
        bump(a.x, u0, hw); bump(a.y, u1, hw);
        bump(a.z, u2, hw); bump(a.w, u3, hw);
    } else {
        bump_slow(u0); bump_slow(u1); bump_slow(u2); bump_slow(u3);
    }
}

__global__ void __launch_bounds__(256) k_hist(const float* __restrict__ x,
                                              int n4, int n) {
    __shared__ unsigned int sh[NPAIR * 256];     // 32 KB
    const int tid = threadIdx.x;
    #pragma unroll
    for (int i = tid; i < NPAIR * 256; i += 256) sh[i] = 0u;
    __syncthreads();

    unsigned int* hw = sh + tid;
    const float4* x4 = (const float4*)x;
    const int st = gridDim.x * 256;

    int idx = blockIdx.x * 256 + tid;
    for (; idx + 3 * st < n4; idx += 4 * st) {   // 4 front-batched float4 loads
        float4 a = __ldg(&x4[idx]);
        float4 b = __ldg(&x4[idx + st]);
        float4 c = __ldg(&x4[idx + 2 * st]);
        float4 d = __ldg(&x4[idx + 3 * st]);
        group4(a, hw); group4(b, hw); group4(c, hw); group4(d, hw);
    }
    for (; idx < n4; idx += st)
        group4(__ldg(&x4[idx]), hw);
    for (int j = n4 * 4 + blockIdx.x * 256 + tid; j < n; j += st) {
        float xv = __ldg(&x[j]);
        unsigned int u = key_of(xv);
        if (u < WBINS) bump(xv, u, hw); else bump_slow(u);
    }
    __syncthreads();

    // merge: warp w reduces bins [w*8, w*8+8); lane-strided columns (bank-free)
    const int wid = tid >> 5, lane = tid & 31;
    for (int b = wid * 8; b < wid * 8 + 8; b++) {
        const unsigned int* col = sh + (b & 31) * 256;
        const int shift = (b & 32) ? 16 : 0;
        unsigned int s = 0;
        #pragma unroll
        for (int c = 0; c < 8; c++)
            s += (col[lane + 32 * c] >> shift) & 0xFFFFu;
        #pragma unroll
        for (int o = 16; o > 0; o >>= 1)
            s += __shfl_down_sync(0xffffffffu, s, o);
        if (lane == 0 && s)
            atomicAdd(&d_hist[b - WOFF + KOFF], s);
    }
}

// ---------------------------------------------------------------- prep (tiny)
__global__ void __launch_bounds__(256) k_prep(int n) {
    __shared__ unsigned int hist[KBINS];
    __shared__ int kmin_sh, kmax_sh;
    if (threadIdx.x == 0) { kmin_sh = KBINS; kmax_sh = -1; }
    for (int b = threadIdx.x; b < KBINS; b += 256) hist[b] = d_hist[b];
    __syncthreads();
    for (int b = threadIdx.x; b < KBINS; b += 256)
        if (hist[b]) { atomicMin(&kmin_sh, b); atomicMax(&kmax_sh, b); }
    __syncthreads();

    if (threadIdx.x == 0) {
        int kmin = kmin_sh - KOFF;                        // lowest key floor(5x)
        int jmin = (kmin >= 0) ? (kmin / 5) : -((-kmin + 4) / 5);  // floor(min)
        int vmin_i = jmin - 1;                            // vmin (integer)
        int shift = 5 * vmin_i;                           // hidx = k - 5*vmin

        float cnt[NBINS_MAX];
        for (int i = 0; i < NBINS_MAX; i++) cnt[i] = 0.0f;
        for (int b = kmin_sh; b <= kmax_sh; b++) {
            unsigned int c = hist[b];
            if (!c) continue;
            int t = (b - KOFF) - shift;
            t = min(NBINS_MAX - 1, max(0, t));
            cnt[t] += (float)c;
        }
        float inv_n = 1.0f / (float)n;
        float c_arr[NBINS_MAX + 1];
        c_arr[0] = 0.0f;
        for (int i = 0; i < NBINS_MAX; i++)
            c_arr[i + 1] = c_arr[i] + cnt[i] * inv_n;
        float hist_add[HLEN];
        for (int i = 0; i < HLEN; i++)
            hist_add[i] = c_arr[i + BPU_I] - c_arr[i];
        double vmn = (double)vmin_i + 0.5;
        for (int i = 0; i < GLEN; i++) {
            float g = (hist_add[i + 1] - hist_add[i]) * 5.0f;
            double left = vmn + (double)i * 0.2;
            double c = (double)hist_add[i] + 1e-8 - left * (double)g;
            d_gh[i] = make_float2(g, (float)c);
        }
        d_voff = (float)(-5.0 * vmn);
    }
}

// ---------------------------------------------------------------- loss
__device__ __forceinline__ float nl_one(float xv, float voff,
                                        const float2* __restrict__ gh) {
    int i = __float2int_rd(fmaf(xv, 5.0f, voff));   // lower clamp provably dead
    i = min(i, GLEN - 1);
    float2 p = gh[i];
    return fmaf(xv, p.x, p.y);                      // (x-left)*g + ha + 1e-8
}

__global__ void __launch_bounds__(256) k_loss(const float* __restrict__ x,
                                              int n4, int n) {
    __shared__ float2 gh[GLEN];
    __shared__ float wsum[8];
    for (int i = threadIdx.x; i < GLEN; i += 256) gh[i] = d_gh[i];
    float voff = d_voff;
    __syncthreads();

    const float4* x4 = (const float4*)x;
    const int st = gridDim.x * 256;
    float acc = 0.0f;

    int idx = blockIdx.x * 256 + threadIdx.x;
    for (; idx + 3 * st < n4; idx += 4 * st) {
        float4 a = __ldg(&x4[idx]);
        float4 b = __ldg(&x4[idx + st]);
        float4 c = __ldg(&x4[idx + 2 * st]);
        float4 d = __ldg(&x4[idx + 3 * st]);
        float pa = nl_one(a.x, voff, gh) * nl_one(a.y, voff, gh)
                 * nl_one(a.z, voff, gh) * nl_one(a.w, voff, gh);
        float pb = nl_one(b.x, voff, gh) * nl_one(b.y, voff, gh)
                 * nl_one(b.z, voff, gh) * nl_one(b.w, voff, gh);
        float pc = nl_one(c.x, voff, gh) * nl_one(c.y, voff, gh)
                 * nl_one(c.z, voff, gh) * nl_one(c.w, voff, gh);
        float pd = nl_one(d.x, voff, gh) * nl_one(d.y, voff, gh)
                 * nl_one(d.z, voff, gh) * nl_one(d.w, voff, gh);
        acc += __log2f(pa); acc += __log2f(pb);
        acc += __log2f(pc); acc += __log2f(pd);
    }
    for (; idx < n4; idx += st) {
        float4 a = __ldg(&x4[idx]);
        float pa = nl_one(a.x, voff, gh) * nl_one(a.y, voff, gh)
                 * nl_one(a.z, voff, gh) * nl_one(a.w, voff, gh);
        acc += __log2f(pa);
    }
    for (int j = n4 * 4 + blockIdx.x * 256 + threadIdx.x; j < n; j += st)
        acc += __log2f(nl_one(__ldg(&x[j]), voff, gh));

    #pragma unroll
    for (int o = 16; o > 0; o >>= 1)
        acc += __shfl_down_sync(0xffffffffu, acc, o);
    int wid = threadIdx.x >> 5, lid = threadIdx.x & 31;
    if (lid == 0) wsum[wid] = acc;
    __syncthreads();
    if (wid == 0) {
        float s = (lid < 8) ? wsum[lid] : 0.0f;
        #pragma unroll
        for (int o = 4; o > 0; o >>= 1)
            s += __shfl_down_sync(0xffffffffu, s, o);
        if (lid == 0) atomicAdd(&d_sum, (double)s);
    }
}

// ---------------------------------------------------------------- finalize + reset
__global__ void __launch_bounds__(256) k_final(float* __restrict__ out, int n) {
    if (threadIdx.x == 0) {
        out[0] = (float)(-d_sum / (double)n);
        d_sum = 0.0;                          // reset for next replay
    }
    for (int i = threadIdx.x; i < KBINS; i += 256)
        d_hist[i] = 0u;                       // reset for next replay
}

// ---------------------------------------------------------------- launch
extern "C" void kernel_launch(void* const* d_in, const int* in_sizes, int n_in,
                              void* d_out, int out_size) {
    const float* x = (const float*)d_in[0];
    int n  = in_sizes[0];
    int n4 = n >> 2;
    const int GRID_H = 1036;  // 7 per SM * 148 (32KB smem/block)
    const int GRID_L = 1184;  // 8 per SM * 148

    k_hist<<<GRID_H, 256>>>(x, n4, n);
    k_prep<<<1, 256>>>(n);
    k_loss<<<GRID_L, 256>>>(x, n4, n);
    k_final<<<1, 256>>>((float*)d_out, n);
}